// round 8
// baseline (speedup 1.0000x reference)
#include <cuda_runtime.h>
#include <cuda_fp16.h>
#include <cstdint>

// Problem constants (fixed by setup_inputs)
#define BB 2
#define LL 4096
#define DD 1024
#define DI 1024
#define NS 16
#define RR 64
#define HH 4096
#define MM (BB*LL)          // 8192 rows
#define PROJC (RR + 2*NS)   // 96

// ---------------- scratch ( __device__ globals, no allocation ) -------------
__device__ __half g_Uh  [(size_t)MM * DD];      // LN(gathered x), fp16
__device__ __half g_XZh [(size_t)MM * 2 * DI];  // in_proj output (xi | z), fp16
__device__ float  g_XC  [(size_t)MM * DI];      // conv + silu (f32 for scan)
__device__ __half g_XCh [(size_t)MM * DI];      // conv + silu (f16 for GEMM)
__device__ float  g_PROJ[(size_t)MM * PROJC];   // x_proj output (f32 for scan B,C)
__device__ __half g_PROJh[(size_t)MM * PROJC];  // fp16 copy for dt GEMM
__device__ float  g_DT  [(size_t)MM * DI];      // softplus(dt)
__device__ __half g_Yh  [(size_t)MM * DI];      // scan output * silu(z), fp16
__device__ float  g_XNEW[(size_t)MM * DD];      // x + scattered mamba out
__device__ __half g_HNh [(size_t)MM * DD];      // LN(xnew), fp16
__device__ __half g_Gh  [(size_t)MM * HH];      // gelu(fc1), fp16
// fp16 weights
__device__ __half g_Wip [(size_t)2 * DI * DD];
__device__ __half g_Wxp [(size_t)PROJC * DI];
__device__ __half g_Wdt [(size_t)DI * RR];
__device__ __half g_Wop [(size_t)DD * DI];
__device__ __half g_Wf1 [(size_t)HH * DD];
__device__ __half g_Wf2 [(size_t)DD * HH];

// ---------------- helpers ---------------------------------------------------
__device__ __forceinline__ float silu_f(float x) { return x / (1.0f + __expf(-x)); }
__device__ __forceinline__ float gelu_tanh_f(float x) {
    float u = 0.7978845608028654f * (x + 0.044715f * x * x * x);
    return 0.5f * x * (1.0f + tanhf(u));
}
__device__ __forceinline__ float softplus_f(float x) {
    return (x > 20.0f) ? x : log1pf(expf(x));
}

// ---------------- all-weights f32 -> f16 convert (single launch) -------------
__global__ __launch_bounds__(256) void f2h_all_kernel(
    const float* __restrict__ s0, __half* __restrict__ d0, int n0,
    const float* __restrict__ s1, __half* __restrict__ d1, int n1,
    const float* __restrict__ s2, __half* __restrict__ d2, int n2,
    const float* __restrict__ s3, __half* __restrict__ d3, int n3,
    const float* __restrict__ s4, __half* __restrict__ d4, int n4,
    const float* __restrict__ s5, __half* __restrict__ d5, int n5)
{
    const float* s; __half* d; int n;
    switch (blockIdx.y) {
        case 0: s = s0; d = d0; n = n0; break;
        case 1: s = s1; d = d1; n = n1; break;
        case 2: s = s2; d = d2; n = n2; break;
        case 3: s = s3; d = d3; n = n3; break;
        case 4: s = s4; d = d4; n = n4; break;
        default: s = s5; d = d5; n = n5; break;
    }
    int i = (blockIdx.x * blockDim.x + threadIdx.x) * 4;
    if (i >= n) return;
    float4 v = *(const float4*)(s + i);
    __half2* dp = (__half2*)(d + i);
    dp[0] = __floats2half2_rn(v.x, v.y);
    dp[1] = __floats2half2_rn(v.z, v.w);
}

// ---------------- LayerNorm (optional gather), fp16 out ---------------------
__global__ __launch_bounds__(256) void ln_kernel(
    const float* __restrict__ X, const int* __restrict__ gather,
    __half* __restrict__ Out)
{
    int row = blockIdx.x;
    int b = row >> 12, t = row & (LL - 1);
    int src = gather ? ((b << 12) + gather[t]) : row;
    const float* xp = X + (size_t)src * DD;
    __half* op = Out + (size_t)row * DD;
    __shared__ float sred[8];
    __shared__ float smv[2];
    int tid = threadIdx.x;

    float v[4];
    float s = 0.f;
#pragma unroll
    for (int i = 0; i < 4; i++) { v[i] = xp[tid + i * 256]; s += v[i]; }
#pragma unroll
    for (int o = 16; o; o >>= 1) s += __shfl_xor_sync(0xffffffffu, s, o);
    if ((tid & 31) == 0) sred[tid >> 5] = s;
    __syncthreads();
    if (tid < 8) {
        s = sred[tid];
#pragma unroll
        for (int o = 4; o; o >>= 1) s += __shfl_xor_sync(0xffu, s, o);
        if (tid == 0) smv[0] = s * (1.0f / DD);
    }
    __syncthreads();
    float mean = smv[0];
    float vs = 0.f;
#pragma unroll
    for (int i = 0; i < 4; i++) { float d = v[i] - mean; vs += d * d; }
#pragma unroll
    for (int o = 16; o; o >>= 1) vs += __shfl_xor_sync(0xffffffffu, vs, o);
    __syncthreads();
    if ((tid & 31) == 0) sred[tid >> 5] = vs;
    __syncthreads();
    if (tid < 8) {
        vs = sred[tid];
#pragma unroll
        for (int o = 4; o; o >>= 1) vs += __shfl_xor_sync(0xffu, vs, o);
        if (tid == 0) smv[1] = rsqrtf(vs * (1.0f / DD) + 1e-6f);
    }
    __syncthreads();
    float inv = smv[1];
#pragma unroll
    for (int i = 0; i < 4; i++) op[tid + i * 256] = __float2half((v[i] - mean) * inv);
}

// ---------------- FP16 tensor-core GEMM (mma.sync, R4-proven shape) ----------
// C[m,n] = epi( sum_k A[m,k]*W[n,k] ), A: MxK half (lda), W: NxK half row-major.
// MODE 1: gelu(acc+bias)->f16      MODE 2: resid+acc+bias->f32
// MODE 3: softplus(acc+bias)->f32  MODE 4: dual f32+f16
// MODE 5: ->f16                    MODE 6: scatter rows via path, resid+acc->f32
// Tile 128x128, BK=32 halfs, 2-stage cp.async (static smem), 8 warps (4m x 2n).

#define BKH 32
#define ROWH 40   // 32 + 8 pad halfs (80B rows: conflict-free)

__device__ __forceinline__ void mma_f16(float c[4], const uint32_t a[4], const uint32_t b[2]) {
    asm volatile(
        "mma.sync.aligned.m16n8k16.row.col.f32.f16.f16.f32 "
        "{%0,%1,%2,%3}, {%4,%5,%6,%7}, {%8,%9}, {%0,%1,%2,%3};\n"
        : "+f"(c[0]), "+f"(c[1]), "+f"(c[2]), "+f"(c[3])
        : "r"(a[0]), "r"(a[1]), "r"(a[2]), "r"(a[3]), "r"(b[0]), "r"(b[1]));
}
__device__ __forceinline__ void ldsm_x4(uint32_t r[4], const void* p) {
    uint32_t s = (uint32_t)__cvta_generic_to_shared(p);
    asm volatile("ldmatrix.sync.aligned.m8n8.x4.shared.b16 {%0,%1,%2,%3}, [%4];\n"
                 : "=r"(r[0]), "=r"(r[1]), "=r"(r[2]), "=r"(r[3]) : "r"(s));
}
__device__ __forceinline__ void cp16(void* dst, const void* src, bool pred) {
    uint32_t d = (uint32_t)__cvta_generic_to_shared(dst);
    int sz = pred ? 16 : 0;
    asm volatile("cp.async.cg.shared.global [%0], [%1], 16, %2;\n"
                 :: "r"(d), "l"(src), "r"(sz));
}

template <int MODE>
__global__ __launch_bounds__(256, 2) void hgemm(
    const __half* __restrict__ A, int lda,
    const __half* __restrict__ W,
    const float* __restrict__ bias,
    const float* __restrict__ resid,
    const int* __restrict__ path,
    float* __restrict__ Cf, __half* __restrict__ Ch,
    int M, int N, int K)
{
    __shared__ __half As[2][128][ROWH];
    __shared__ __half Ws[2][128][ROWH];

    int tid  = threadIdx.x;
    int warp = tid >> 5, lane = tid & 31;
    int g = lane >> 2, t = lane & 3;
    int wm = warp >> 1, wn = warp & 1;     // 4 x 2 warp grid
    int row0 = blockIdx.y * 128;
    int col0 = blockIdx.x * 128;

    // global->smem mapping: thread -> (row = tid>>1), two 16B chunks
    int lrow = tid >> 1;
    int lch  = (tid & 1) * 16;             // half offset of first chunk
    const __half* Ag = A + (size_t)(row0 + lrow) * lda + lch;
    int wnrow = col0 + lrow;
    bool wok = (wnrow < N);
    const __half* Wg = W + (size_t)(wok ? wnrow : 0) * K + lch;

    float acc[2][8][4];
#pragma unroll
    for (int i = 0; i < 2; i++)
#pragma unroll
        for (int j = 0; j < 8; j++)
#pragma unroll
            for (int q = 0; q < 4; q++) acc[i][j][q] = 0.f;

#define LOADST(k0, b)                                                     \
    {                                                                     \
        cp16(&As[b][lrow][lch + 0], Ag + (k0) + 0, true);                 \
        cp16(&As[b][lrow][lch + 8], Ag + (k0) + 8, true);                 \
        cp16(&Ws[b][lrow][lch + 0], Wg + (k0) + 0, wok);                  \
        cp16(&Ws[b][lrow][lch + 8], Wg + (k0) + 8, wok);                  \
        asm volatile("cp.async.commit_group;\n");                         \
    }

#define COMPUTE(b)                                                        \
    {                                                                     \
        _Pragma("unroll")                                                 \
        for (int ks = 0; ks < BKH; ks += 16) {                            \
            uint32_t af[2][4], bf[8][2];                                  \
            _Pragma("unroll")                                             \
            for (int i = 0; i < 2; i++)                                   \
                ldsm_x4(af[i], &As[b][wm * 32 + i * 16 + (lane & 15)]     \
                                   [ks + (lane >> 4) * 8]);               \
            _Pragma("unroll")                                             \
            for (int j = 0; j < 8; j++) {                                 \
                const __half* wp = &Ws[b][wn * 64 + j * 8 + g][ks + 2*t]; \
                bf[j][0] = *(const uint32_t*)wp;                          \
                bf[j][1] = *(const uint32_t*)(wp + 8);                    \
            }                                                             \
            _Pragma("unroll")                                             \
            for (int i = 0; i < 2; i++)                                   \
                _Pragma("unroll")                                         \
                for (int j = 0; j < 8; j++)                               \
                    mma_f16(acc[i][j], af[i], bf[j]);                     \
        }                                                                 \
    }

    LOADST(0, 0);
    int buf = 0;
    for (int k0 = BKH; k0 < K; k0 += BKH) {
        LOADST(k0, buf ^ 1);
        asm volatile("cp.async.wait_group 1;\n");
        __syncthreads();
        COMPUTE(buf);
        __syncthreads();
        buf ^= 1;
    }
    asm volatile("cp.async.wait_group 0;\n");
    __syncthreads();
    COMPUTE(buf);

    // epilogue: each thread owns cols (2t, 2t+1), rows g / g+8 per 16-row tile
#pragma unroll
    for (int i = 0; i < 2; i++) {
#pragma unroll
        for (int j = 0; j < 8; j++) {
            int col = col0 + wn * 64 + j * 8 + 2 * t;
            if (col >= N) continue;
            float b0v = 0.f, b1v = 0.f;
            if (MODE == 1 || MODE == 2 || MODE == 3) { b0v = bias[col]; b1v = bias[col + 1]; }
#pragma unroll
            for (int h = 0; h < 2; h++) {
                int row = row0 + wm * 32 + i * 16 + g + h * 8;
                float v0 = acc[i][j][2 * h + 0];
                float v1 = acc[i][j][2 * h + 1];
                if (MODE == 6) {
                    int dest = (row & ~(LL - 1)) + path[row & (LL - 1)];
                    size_t oidx = (size_t)dest * N + col;
                    float2 rr = *(const float2*)(resid + oidx);
                    *(float2*)(Cf + oidx) = make_float2(rr.x + v0, rr.y + v1);
                    continue;
                }
                size_t oidx = (size_t)row * N + col;
                if (MODE == 1) {
                    v0 = gelu_tanh_f(v0 + b0v); v1 = gelu_tanh_f(v1 + b1v);
                    *(__half2*)(Ch + oidx) = __floats2half2_rn(v0, v1);
                } else if (MODE == 2) {
                    float2 rr = *(const float2*)(resid + oidx);
                    *(float2*)(Cf + oidx) = make_float2(rr.x + v0 + b0v, rr.y + v1 + b1v);
                } else if (MODE == 3) {
                    *(float2*)(Cf + oidx) = make_float2(softplus_f(v0 + b0v),
                                                        softplus_f(v1 + b1v));
                } else if (MODE == 4) {
                    *(float2*)(Cf + oidx) = make_float2(v0, v1);
                    *(__half2*)(Ch + oidx) = __floats2half2_rn(v0, v1);
                } else if (MODE == 5) {
                    *(__half2*)(Ch + oidx) = __floats2half2_rn(v0, v1);
                }
            }
        }
    }
#undef LOADST
#undef COMPUTE
}

// ---------------- depthwise causal conv (D_CONV=4) + silu -------------------
__global__ __launch_bounds__(256) void conv_silu_kernel(
    const __half* __restrict__ XZ, const float* __restrict__ conv_w,
    const float* __restrict__ conv_b, float* __restrict__ XC,
    __half* __restrict__ XCh)
{
    size_t idx = (size_t)blockIdx.x * blockDim.x + threadIdx.x;
    if (idx >= (size_t)MM * DI) return;
    int d = (int)(idx & (DI - 1));
    int m = (int)(idx >> 10);
    int t = m & (LL - 1);
    int mb = m - t;
    float acc = conv_b[d];
#pragma unroll
    for (int k = 0; k < 4; k++) {
        int tt = t - 3 + k;
        if (tt >= 0)
            acc = fmaf(conv_w[d * 4 + k],
                       __half2float(XZ[(size_t)(mb + tt) * (2 * DI) + d]), acc);
    }
    float r = silu_f(acc);
    XC[idx] = r;
    XCh[idx] = __float2half(r);
}

// ---------------- selective scan: warp per (b,d), prefetched (R4-proven) -----
__global__ __launch_bounds__(256) void scan_kernel(
    const float* __restrict__ DT, const float* __restrict__ XC,
    const float* __restrict__ PROJ, const __half* __restrict__ XZ,
    const float* __restrict__ A_log, const float* __restrict__ D_param,
    __half* __restrict__ Y)
{
    int wg = (blockIdx.x * blockDim.x + threadIdx.x) >> 5;  // 0..2047
    int lane = threadIdx.x & 31;
    int b = wg >> 10;
    int d = wg & (DI - 1);
    bool act = lane < NS;
    float A_n = act ? -expf(A_log[d * NS + lane]) : 0.f;
    float Dp = D_param[d];

    const float* dtp = DT + (size_t)b * LL * DI + d;
    const float* xcp = XC + (size_t)b * LL * DI + d;
    const __half* zp = XZ + (size_t)b * LL * (2 * DI) + DI + d;
    const float* bcp = PROJ + (size_t)b * LL * PROJC + RR;
    __half* yp = Y + (size_t)b * LL * DI + d;

    float h = 0.f;
    float dt = __ldg(dtp), xc = __ldg(xcp);
    float zv = __half2float(__ldg(zp));
    float bcv = __ldg(bcp + lane);
    for (int t = 0; t < LL; t++) {
        float ndt = 0.f, nxc = 0.f, nzv = 0.f, nbcv = 0.f;
        if (t + 1 < LL) {
            ndt = __ldg(dtp + DI);
            nxc = __ldg(xcp + DI);
            nzv = __half2float(__ldg(zp + 2 * DI));
            nbcv = __ldg(bcp + PROJC + lane);
        }
        float Cv = __shfl_down_sync(0xffffffffu, bcv, 16);
        float Bv = act ? bcv : 0.f;
        Cv = act ? Cv : 0.f;

        float dA = __expf(dt * A_n);
        h = fmaf(dA, h, dt * xc * Bv);
        float part = h * Cv;                   // nonzero only in lanes 0-15
#pragma unroll
        for (int o = 8; o; o >>= 1) part += __shfl_xor_sync(0xffffffffu, part, o);
        if (lane == 0) {
            float y = part + Dp * xc;
            *yp = __float2half(y * silu_f(zv));
        }
        dtp += DI; xcp += DI; zp += 2 * DI; bcp += PROJC; yp += DI;
        dt = ndt; xc = nxc; zv = nzv; bcv = nbcv;
    }
}

// ---------------- launch -----------------------------------------------------
extern "C" void kernel_launch(void* const* d_in, const int* in_sizes, int n_in,
                              void* d_out, int out_size)
{
    const float* x          = (const float*)d_in[0];
    const int*   path       = (const int*)  d_in[1];
    const int*   path_rev   = (const int*)  d_in[2];
    const float* in_proj_w  = (const float*)d_in[3];
    const float* conv_w     = (const float*)d_in[4];
    const float* conv_b     = (const float*)d_in[5];
    const float* x_proj_w   = (const float*)d_in[6];
    const float* dt_proj_w  = (const float*)d_in[7];
    const float* dt_proj_b  = (const float*)d_in[8];
    const float* A_log      = (const float*)d_in[9];
    const float* D_param    = (const float*)d_in[10];
    const float* out_proj_w = (const float*)d_in[11];
    const float* fc1_w      = (const float*)d_in[12];
    const float* fc1_b      = (const float*)d_in[13];
    const float* fc2_w      = (const float*)d_in[14];
    const float* fc2_b      = (const float*)d_in[15];
    float* out = (float*)d_out;
    (void)path_rev;

    __half *Uh, *XZh, *XCh, *PROJh, *Yh, *HNh, *Gh;
    __half *Wip, *Wxp, *Wdt, *Wop, *Wf1, *Wf2;
    float *XC, *PROJ, *DT, *XNEW;
    cudaGetSymbolAddress((void**)&Uh,    g_Uh);
    cudaGetSymbolAddress((void**)&XZh,   g_XZh);
    cudaGetSymbolAddress((void**)&XC,    g_XC);
    cudaGetSymbolAddress((void**)&XCh,   g_XCh);
    cudaGetSymbolAddress((void**)&PROJ,  g_PROJ);
    cudaGetSymbolAddress((void**)&PROJh, g_PROJh);
    cudaGetSymbolAddress((void**)&DT,    g_DT);
    cudaGetSymbolAddress((void**)&Yh,    g_Yh);
    cudaGetSymbolAddress((void**)&XNEW,  g_XNEW);
    cudaGetSymbolAddress((void**)&HNh,   g_HNh);
    cudaGetSymbolAddress((void**)&Gh,    g_Gh);
    cudaGetSymbolAddress((void**)&Wip,   g_Wip);
    cudaGetSymbolAddress((void**)&Wxp,   g_Wxp);
    cudaGetSymbolAddress((void**)&Wdt,   g_Wdt);
    cudaGetSymbolAddress((void**)&Wop,   g_Wop);
    cudaGetSymbolAddress((void**)&Wf1,   g_Wf1);
    cudaGetSymbolAddress((void**)&Wf2,   g_Wf2);

    // 0. all weights -> fp16 in ONE launch
    {
        dim3 grid((4 * 1024 * 1024 / 4 + 255) / 256, 6);  // x sized for largest (fc1/fc2)
        f2h_all_kernel<<<grid, 256>>>(
            in_proj_w,  Wip, 2 * DI * DD,
            x_proj_w,   Wxp, PROJC * DI,
            dt_proj_w,  Wdt, DI * RR,
            out_proj_w, Wop, DD * DI,
            fc1_w,      Wf1, HH * DD,
            fc2_w,      Wf2, DD * HH);
    }

    // 1. u = LN(x[:, path, :]) -> fp16
    ln_kernel<<<MM, 256>>>(x, path, Uh);

    // 2. xz = u @ in_proj_w^T   (8192 x 2048, K=1024) -> fp16
    hgemm<5><<<dim3(2 * DI / 128, MM / 128), 256>>>(
        Uh, DD, Wip, nullptr, nullptr, nullptr, nullptr, XZh, MM, 2 * DI, DD);

    // 3. conv + silu -> f32 + f16
    conv_silu_kernel<<<(int)(((size_t)MM * DI + 255) / 256), 256>>>(XZh, conv_w, conv_b, XC, XCh);

    // 4. proj = xc @ x_proj_w^T   (8192 x 96, K=1024) -> f32 + f16
    hgemm<4><<<dim3(1, MM / 128), 256>>>(
        XCh, DI, Wxp, nullptr, nullptr, nullptr, PROJ, PROJh, MM, PROJC, DI);

    // 5. dt = softplus(proj[:, :64] @ dt_proj_w^T + b)   (8192 x 1024, K=64)
    //    -> launch #6: ncu -s 5 -c 1 captures THIS hgemm
    hgemm<3><<<dim3(DI / 128, MM / 128), 256>>>(
        PROJh, PROJC, Wdt, dt_proj_b, nullptr, nullptr, DT, nullptr, MM, DI, RR);

    // 6. selective scan -> Yh
    scan_kernel<<<(BB * DI * 32) / 256, 256>>>(DT, XC, PROJ, XZh, A_log, D_param, Yh);

    // 7+8. XNEW = x + scatter(Y @ out_proj_w^T)   (8192 x 1024, K=1024)
    hgemm<6><<<dim3(DD / 128, MM / 128), 256>>>(
        Yh, DI, Wop, nullptr, x, path, XNEW, nullptr, MM, DD, DI);

    // 9. hn = LN(xnew) -> fp16
    ln_kernel<<<MM, 256>>>(XNEW, nullptr, HNh);

    // 10. G = gelu(hn @ fc1_w^T + fc1_b)   (8192 x 4096, K=1024) -> fp16
    hgemm<1><<<dim3(HH / 128, MM / 128), 256>>>(
        HNh, DD, Wf1, fc1_b, nullptr, nullptr, nullptr, Gh, MM, HH, DD);

    // 11. out = xnew + G @ fc2_w^T + fc2_b   (8192 x 1024, K=4096)
    hgemm<2><<<dim3(DD / 128, MM / 128), 256>>>(
        Gh, HH, Wf2, fc2_b, XNEW, nullptr, out, nullptr, MM, DD, HH);
}

// round 10
// speedup vs baseline: 1.5792x; 1.5792x over previous
#include <cuda_runtime.h>
#include <cuda_fp16.h>
#include <cstdint>

// Problem constants (fixed by setup_inputs)
#define BB 2
#define LL 4096
#define DD 1024
#define DI 1024
#define NS 16
#define RR 64
#define HH 4096
#define MM (BB*LL)          // 8192 rows
#define PROJC (RR + 2*NS)   // 96

// ---------------- scratch ( __device__ globals, no allocation ) -------------
__device__ __half g_Uh  [(size_t)MM * DD];      // LN(gathered x), fp16
__device__ float  g_XZ  [(size_t)MM * 2 * DI];  // in_proj output (xi | z)
__device__ float  g_XC  [(size_t)MM * DI];      // conv + silu (f32 for scan)
__device__ __half g_XCh [(size_t)MM * DI];      // conv + silu (f16 for GEMM)
__device__ float  g_PROJ[(size_t)MM * PROJC];   // x_proj output (f32 for scan B,C)
__device__ __half g_PROJh[(size_t)MM * PROJC];  // fp16 copy for dt GEMM
__device__ float  g_DT  [(size_t)MM * DI];      // softplus(dt)
__device__ __half g_Yh  [(size_t)MM * DI];      // scan output * silu(z), fp16
__device__ float  g_OUTP[(size_t)MM * DD];      // out_proj output
__device__ float  g_XNEW[(size_t)MM * DD];      // x + scattered mamba out
__device__ __half g_HNh [(size_t)MM * DD];      // LN(xnew), fp16
__device__ __half g_Gh  [(size_t)MM * HH];      // gelu(fc1), fp16
// fp16 weights
__device__ __half g_Wip [(size_t)2 * DI * DD];
__device__ __half g_Wxp [(size_t)PROJC * DI];
__device__ __half g_Wdt [(size_t)DI * RR];
__device__ __half g_Wop [(size_t)DD * DI];
__device__ __half g_Wf1 [(size_t)HH * DD];
__device__ __half g_Wf2 [(size_t)DD * HH];

// ---------------- helpers ---------------------------------------------------
__device__ __forceinline__ float silu_f(float x) { return x / (1.0f + __expf(-x)); }
__device__ __forceinline__ float gelu_tanh_f(float x) {
    float u = 0.7978845608028654f * (x + 0.044715f * x * x * x);
    return 0.5f * x * (1.0f + tanhf(u));
}
__device__ __forceinline__ float softplus_f(float x) {
    return (x > 20.0f) ? x : log1pf(expf(x));
}

// ---------------- f32 -> f16 convert ----------------------------------------
__global__ __launch_bounds__(256) void f2h_kernel(const float* __restrict__ s,
                                                  __half* __restrict__ d, int n)
{
    int i = (blockIdx.x * blockDim.x + threadIdx.x) * 4;
    if (i >= n) return;
    float4 v = *(const float4*)(s + i);
    __half2* dp = (__half2*)(d + i);
    dp[0] = __floats2half2_rn(v.x, v.y);
    dp[1] = __floats2half2_rn(v.z, v.w);
}

// ---------------- LayerNorm (optional gather), fp16 out ---------------------
__global__ __launch_bounds__(256) void ln_kernel(
    const float* __restrict__ X, const int* __restrict__ gather,
    __half* __restrict__ Out)
{
    int row = blockIdx.x;
    int b = row >> 12, t = row & (LL - 1);
    int src = gather ? ((b << 12) + gather[t]) : row;
    const float* xp = X + (size_t)src * DD;
    __half* op = Out + (size_t)row * DD;
    __shared__ float sred[8];
    __shared__ float smv[2];
    int tid = threadIdx.x;

    float v[4];
    float s = 0.f;
#pragma unroll
    for (int i = 0; i < 4; i++) { v[i] = xp[tid + i * 256]; s += v[i]; }
#pragma unroll
    for (int o = 16; o; o >>= 1) s += __shfl_xor_sync(0xffffffffu, s, o);
    if ((tid & 31) == 0) sred[tid >> 5] = s;
    __syncthreads();
    if (tid < 8) {
        s = sred[tid];
#pragma unroll
        for (int o = 4; o; o >>= 1) s += __shfl_xor_sync(0xffu, s, o);
        if (tid == 0) smv[0] = s * (1.0f / DD);
    }
    __syncthreads();
    float mean = smv[0];
    float vs = 0.f;
#pragma unroll
    for (int i = 0; i < 4; i++) { float d = v[i] - mean; vs += d * d; }
#pragma unroll
    for (int o = 16; o; o >>= 1) vs += __shfl_xor_sync(0xffffffffu, vs, o);
    __syncthreads();
    if ((tid & 31) == 0) sred[tid >> 5] = vs;
    __syncthreads();
    if (tid < 8) {
        vs = sred[tid];
#pragma unroll
        for (int o = 4; o; o >>= 1) vs += __shfl_xor_sync(0xffu, vs, o);
        if (tid == 0) smv[1] = rsqrtf(vs * (1.0f / DD) + 1e-6f);
    }
    __syncthreads();
    float inv = smv[1];
#pragma unroll
    for (int i = 0; i < 4; i++) op[tid + i * 256] = __float2half((v[i] - mean) * inv);
}

// ---------------- FP16 tensor-core GEMM (mma.sync) ---------------------------
// C[m,n] = epi( sum_k A[m,k]*W[n,k] ), A: MxK half (lda), W: NxK half row-major.
// MODE 0: f32 out   1: gelu(acc+bias)->f16   2: resid+acc+bias->f32
// MODE 3: softplus(acc+bias)->f32            4: dual f32 + f16
// Tile 128x128, BK=32 halfs, *** 3-stage *** cp.async pipeline (dynamic smem).

#define BKH 32
#define ROWH 40   // 32 + 8 pad halfs (80B rows: conflict-free)
#define NSTG 3
#define HG_SMEM (NSTG * 2 * 128 * ROWH * 2)   // 61440 bytes

__device__ __forceinline__ void mma_f16(float c[4], const uint32_t a[4], const uint32_t b[2]) {
    asm volatile(
        "mma.sync.aligned.m16n8k16.row.col.f32.f16.f16.f32 "
        "{%0,%1,%2,%3}, {%4,%5,%6,%7}, {%8,%9}, {%0,%1,%2,%3};\n"
        : "+f"(c[0]), "+f"(c[1]), "+f"(c[2]), "+f"(c[3])
        : "r"(a[0]), "r"(a[1]), "r"(a[2]), "r"(a[3]), "r"(b[0]), "r"(b[1]));
}
__device__ __forceinline__ void ldsm_x4(uint32_t r[4], const void* p) {
    uint32_t s = (uint32_t)__cvta_generic_to_shared(p);
    asm volatile("ldmatrix.sync.aligned.m8n8.x4.shared.b16 {%0,%1,%2,%3}, [%4];\n"
                 : "=r"(r[0]), "=r"(r[1]), "=r"(r[2]), "=r"(r[3]) : "r"(s));
}
__device__ __forceinline__ void cp16(void* dst, const void* src, bool pred) {
    uint32_t d = (uint32_t)__cvta_generic_to_shared(dst);
    int sz = pred ? 16 : 0;
    asm volatile("cp.async.cg.shared.global [%0], [%1], 16, %2;\n"
                 :: "r"(d), "l"(src), "r"(sz));
}

template <int MODE>
__global__ __launch_bounds__(256, 2) void hgemm(
    const __half* __restrict__ A, int lda,
    const __half* __restrict__ W,
    const float* __restrict__ bias,
    const float* __restrict__ resid,
    float* __restrict__ Cf, __half* __restrict__ Ch,
    int M, int N, int K)
{
    extern __shared__ __half dsm[];
    typedef __half Stage[128][ROWH];
    Stage* As = (Stage*)dsm;                         // As[0..2]
    Stage* Ws = (Stage*)(dsm + NSTG * 128 * ROWH);   // Ws[0..2]

    int tid  = threadIdx.x;
    int warp = tid >> 5, lane = tid & 31;
    int g = lane >> 2, t = lane & 3;
    int wm = warp >> 1, wn = warp & 1;     // 4 x 2 warp grid
    int row0 = blockIdx.y * 128;
    int col0 = blockIdx.x * 128;

    // global->smem mapping: thread -> (row = tid>>1), two 16B chunks
    int lrow = tid >> 1;
    int lch  = (tid & 1) * 16;             // half offset of first chunk
    const __half* Ag = A + (size_t)(row0 + lrow) * lda + lch;
    int wnrow = col0 + lrow;
    bool wok = (wnrow < N);
    const __half* Wg = W + (size_t)(wok ? wnrow : 0) * K + lch;

    float acc[2][8][4];
#pragma unroll
    for (int i = 0; i < 2; i++)
#pragma unroll
        for (int j = 0; j < 8; j++)
#pragma unroll
            for (int q = 0; q < 4; q++) acc[i][j][q] = 0.f;

#define LOADST(k0, b)                                                     \
    {                                                                     \
        cp16(&As[b][lrow][lch + 0], Ag + (k0) + 0, true);                 \
        cp16(&As[b][lrow][lch + 8], Ag + (k0) + 8, true);                 \
        cp16(&Ws[b][lrow][lch + 0], Wg + (k0) + 0, wok);                  \
        cp16(&Ws[b][lrow][lch + 8], Wg + (k0) + 8, wok);                  \
        asm volatile("cp.async.commit_group;\n");                         \
    }

#define COMPUTE(b)                                                        \
    {                                                                     \
        _Pragma("unroll")                                                 \
        for (int ks = 0; ks < BKH; ks += 16) {                            \
            uint32_t af[2][4], bf[8][2];                                  \
            _Pragma("unroll")                                             \
            for (int i = 0; i < 2; i++)                                   \
                ldsm_x4(af[i], &As[b][wm * 32 + i * 16 + (lane & 15)]     \
                                   [ks + (lane >> 4) * 8]);               \
            _Pragma("unroll")                                             \
            for (int j = 0; j < 8; j++) {                                 \
                const __half* wp = &Ws[b][wn * 64 + j * 8 + g][ks + 2*t]; \
                bf[j][0] = *(const uint32_t*)wp;                          \
                bf[j][1] = *(const uint32_t*)(wp + 8);                    \
            }                                                             \
            _Pragma("unroll")                                             \
            for (int i = 0; i < 2; i++)                                   \
                _Pragma("unroll")                                         \
                for (int j = 0; j < 8; j++)                               \
                    mma_f16(acc[i][j], af[i], bf[j]);                     \
        }                                                                 \
    }

    int NC = K / BKH;
    LOADST(0, 0);
    if (NC > 1) LOADST(BKH, 1);
    if (NC > 2) LOADST(2 * BKH, 2);
    int buf = 0;
    for (int c = 0; c < NC; c++) {
        int rem = NC - 1 - c;   // chunks still to compute after this one
        if (rem >= 2)      asm volatile("cp.async.wait_group 2;\n");
        else if (rem == 1) asm volatile("cp.async.wait_group 1;\n");
        else               asm volatile("cp.async.wait_group 0;\n");
        __syncthreads();
        COMPUTE(buf);
        __syncthreads();
        if (c + 3 < NC) LOADST((c + 3) * BKH, buf);
        buf = (buf == NSTG - 1) ? 0 : buf + 1;
    }

    // epilogue: each thread owns cols (2t, 2t+1), rows g / g+8 per 16-row tile
#pragma unroll
    for (int i = 0; i < 2; i++) {
#pragma unroll
        for (int j = 0; j < 8; j++) {
            int col = col0 + wn * 64 + j * 8 + 2 * t;
            if (col >= N) continue;
            float b0v = 0.f, b1v = 0.f;
            if (MODE == 1 || MODE == 2 || MODE == 3) { b0v = bias[col]; b1v = bias[col + 1]; }
#pragma unroll
            for (int h = 0; h < 2; h++) {
                int row = row0 + wm * 32 + i * 16 + g + h * 8;
                size_t oidx = (size_t)row * N + col;
                float v0 = acc[i][j][2 * h + 0];
                float v1 = acc[i][j][2 * h + 1];
                if (MODE == 1) {
                    v0 = gelu_tanh_f(v0 + b0v); v1 = gelu_tanh_f(v1 + b1v);
                    *(__half2*)(Ch + oidx) = __floats2half2_rn(v0, v1);
                } else if (MODE == 2) {
                    float2 rr = *(const float2*)(resid + oidx);
                    *(float2*)(Cf + oidx) = make_float2(rr.x + v0 + b0v, rr.y + v1 + b1v);
                } else if (MODE == 3) {
                    *(float2*)(Cf + oidx) = make_float2(softplus_f(v0 + b0v),
                                                        softplus_f(v1 + b1v));
                } else if (MODE == 4) {
                    *(float2*)(Cf + oidx) = make_float2(v0, v1);
                    *(__half2*)(Ch + oidx) = __floats2half2_rn(v0, v1);
                } else {
                    *(float2*)(Cf + oidx) = make_float2(v0, v1);
                }
            }
        }
    }
#undef LOADST
#undef COMPUTE
}

// ---------------- depthwise causal conv (D_CONV=4) + silu -------------------
__global__ __launch_bounds__(256) void conv_silu_kernel(
    const float* __restrict__ XZ, const float* __restrict__ conv_w,
    const float* __restrict__ conv_b, float* __restrict__ XC,
    __half* __restrict__ XCh)
{
    size_t idx = (size_t)blockIdx.x * blockDim.x + threadIdx.x;
    if (idx >= (size_t)MM * DI) return;
    int d = (int)(idx & (DI - 1));
    int m = (int)(idx >> 10);
    int t = m & (LL - 1);
    int mb = m - t;
    float acc = conv_b[d];
#pragma unroll
    for (int k = 0; k < 4; k++) {
        int tt = t - 3 + k;
        if (tt >= 0)
            acc = fmaf(conv_w[d * 4 + k], XZ[(size_t)(mb + tt) * (2 * DI) + d], acc);
    }
    float r = silu_f(acc);
    XC[idx] = r;
    XCh[idx] = __float2half(r);
}

// ---------------- selective scan: warp per (b,d), prefetched -----------------
__global__ __launch_bounds__(256) void scan_kernel(
    const float* __restrict__ DT, const float* __restrict__ XC,
    const float* __restrict__ PROJ, const float* __restrict__ XZ,
    const float* __restrict__ A_log, const float* __restrict__ D_param,
    __half* __restrict__ Y)
{
    int wg = (blockIdx.x * blockDim.x + threadIdx.x) >> 5;  // 0..2047
    int lane = threadIdx.x & 31;
    int b = wg >> 10;
    int d = wg & (DI - 1);
    bool act = lane < NS;
    float A_n = act ? -expf(A_log[d * NS + lane]) : 0.f;
    float Dp = D_param[d];

    const float* dtp = DT + (size_t)b * LL * DI + d;
    const float* xcp = XC + (size_t)b * LL * DI + d;
    const float* zp  = XZ + (size_t)b * LL * (2 * DI) + DI + d;
    const float* bcp = PROJ + (size_t)b * LL * PROJC + RR;
    __half* yp = Y + (size_t)b * LL * DI + d;

    float h = 0.f;
    float dt = __ldg(dtp), xc = __ldg(xcp), zv = __ldg(zp), bcv = __ldg(bcp + lane);
    for (int t = 0; t < LL; t++) {
        float ndt = 0.f, nxc = 0.f, nzv = 0.f, nbcv = 0.f;
        if (t + 1 < LL) {
            ndt = __ldg(dtp + DI);
            nxc = __ldg(xcp + DI);
            nzv = __ldg(zp + 2 * DI);
            nbcv = __ldg(bcp + PROJC + lane);
        }
        float Cv = __shfl_down_sync(0xffffffffu, bcv, 16);
        float Bv = act ? bcv : 0.f;
        Cv = act ? Cv : 0.f;

        float dA = __expf(dt * A_n);
        h = fmaf(dA, h, dt * xc * Bv);
        float part = h * Cv;                   // nonzero only in lanes 0-15
#pragma unroll
        for (int o = 8; o; o >>= 1) part += __shfl_xor_sync(0xffffffffu, part, o);
        if (lane == 0) {
            float y = part + Dp * xc;
            *yp = __float2half(y * silu_f(zv));
        }
        dtp += DI; xcp += DI; zp += 2 * DI; bcp += PROJC; yp += DI;
        dt = ndt; xc = nxc; zv = nzv; bcv = nbcv;
    }
}

// ---------------- residual add with gather ----------------------------------
__global__ __launch_bounds__(256) void add_gather_kernel(
    const float* __restrict__ X, const float* __restrict__ OUTP,
    const int* __restrict__ path_rev, float* __restrict__ XNEW)
{
    size_t idx = (size_t)blockIdx.x * blockDim.x + threadIdx.x;
    if (idx >= (size_t)MM * DD) return;
    int d = (int)(idx & (DD - 1));
    int m = (int)(idx >> 10);
    int b = m >> 12, t = m & (LL - 1);
    int src = (b << 12) + path_rev[t];
    XNEW[idx] = X[idx] + OUTP[(size_t)src * DD + d];
}

// ---------------- launch -----------------------------------------------------
extern "C" void kernel_launch(void* const* d_in, const int* in_sizes, int n_in,
                              void* d_out, int out_size)
{
    const float* x          = (const float*)d_in[0];
    const int*   path       = (const int*)  d_in[1];
    const int*   path_rev   = (const int*)  d_in[2];
    const float* in_proj_w  = (const float*)d_in[3];
    const float* conv_w     = (const float*)d_in[4];
    const float* conv_b     = (const float*)d_in[5];
    const float* x_proj_w   = (const float*)d_in[6];
    const float* dt_proj_w  = (const float*)d_in[7];
    const float* dt_proj_b  = (const float*)d_in[8];
    const float* A_log      = (const float*)d_in[9];
    const float* D_param    = (const float*)d_in[10];
    const float* out_proj_w = (const float*)d_in[11];
    const float* fc1_w      = (const float*)d_in[12];
    const float* fc1_b      = (const float*)d_in[13];
    const float* fc2_w      = (const float*)d_in[14];
    const float* fc2_b      = (const float*)d_in[15];
    float* out = (float*)d_out;

    __half *Uh, *XCh, *PROJh, *Yh, *HNh, *Gh;
    __half *Wip, *Wxp, *Wdt, *Wop, *Wf1, *Wf2;
    float *XZ, *XC, *PROJ, *DT, *OUTP, *XNEW;
    cudaGetSymbolAddress((void**)&Uh,    g_Uh);
    cudaGetSymbolAddress((void**)&XZ,    g_XZ);
    cudaGetSymbolAddress((void**)&XC,    g_XC);
    cudaGetSymbolAddress((void**)&XCh,   g_XCh);
    cudaGetSymbolAddress((void**)&PROJ,  g_PROJ);
    cudaGetSymbolAddress((void**)&PROJh, g_PROJh);
    cudaGetSymbolAddress((void**)&DT,    g_DT);
    cudaGetSymbolAddress((void**)&Yh,    g_Yh);
    cudaGetSymbolAddress((void**)&OUTP,  g_OUTP);
    cudaGetSymbolAddress((void**)&XNEW,  g_XNEW);
    cudaGetSymbolAddress((void**)&HNh,   g_HNh);
    cudaGetSymbolAddress((void**)&Gh,    g_Gh);
    cudaGetSymbolAddress((void**)&Wip,   g_Wip);
    cudaGetSymbolAddress((void**)&Wxp,   g_Wxp);
    cudaGetSymbolAddress((void**)&Wdt,   g_Wdt);
    cudaGetSymbolAddress((void**)&Wop,   g_Wop);
    cudaGetSymbolAddress((void**)&Wf1,   g_Wf1);
    cudaGetSymbolAddress((void**)&Wf2,   g_Wf2);

    cudaFuncSetAttribute(hgemm<0>, cudaFuncAttributeMaxDynamicSharedMemorySize, HG_SMEM);
    cudaFuncSetAttribute(hgemm<1>, cudaFuncAttributeMaxDynamicSharedMemorySize, HG_SMEM);
    cudaFuncSetAttribute(hgemm<2>, cudaFuncAttributeMaxDynamicSharedMemorySize, HG_SMEM);
    cudaFuncSetAttribute(hgemm<3>, cudaFuncAttributeMaxDynamicSharedMemorySize, HG_SMEM);
    cudaFuncSetAttribute(hgemm<4>, cudaFuncAttributeMaxDynamicSharedMemorySize, HG_SMEM);

    // 0. weights -> fp16 (separate launches, R4-proven)
    auto cvt = [&](const float* s, __half* d, int n) {
        f2h_kernel<<<(n / 4 + 255) / 256, 256>>>(s, d, n);
    };
    cvt(in_proj_w,  Wip, 2 * DI * DD);
    cvt(x_proj_w,   Wxp, PROJC * DI);
    cvt(dt_proj_w,  Wdt, DI * RR);
    cvt(out_proj_w, Wop, DD * DI);
    cvt(fc1_w,      Wf1, HH * DD);
    cvt(fc2_w,      Wf2, DD * HH);

    // 1. u = LN(x[:, path, :]) -> fp16
    ln_kernel<<<MM, 256>>>(x, path, Uh);

    // 2. xz = u @ in_proj_w^T   (8192 x 2048, K=1024) -> f32
    hgemm<0><<<dim3(2 * DI / 128, MM / 128), 256, HG_SMEM>>>(
        Uh, DD, Wip, nullptr, nullptr, XZ, nullptr, MM, 2 * DI, DD);

    // 3. conv + silu -> f32 + f16
    conv_silu_kernel<<<(int)(((size_t)MM * DI + 255) / 256), 256>>>(XZ, conv_w, conv_b, XC, XCh);

    // 4. proj = xc @ x_proj_w^T   (8192 x 96, K=1024) -> f32 + f16
    hgemm<4><<<dim3(1, MM / 128), 256, HG_SMEM>>>(
        XCh, DI, Wxp, nullptr, nullptr, PROJ, PROJh, MM, PROJC, DI);

    // 5. dt = softplus(proj[:, :64] @ dt_proj_w^T + b)   (8192 x 1024, K=64)
    hgemm<3><<<dim3(DI / 128, MM / 128), 256, HG_SMEM>>>(
        PROJh, PROJC, Wdt, dt_proj_b, nullptr, DT, nullptr, MM, DI, RR);

    // 6. selective scan -> Yh = ((scan + D*xc) * silu(z)) fp16
    scan_kernel<<<(BB * DI * 32) / 256, 256>>>(DT, XC, PROJ, XZ, A_log, D_param, Yh);

    // 7. OUTP = Y @ out_proj_w^T   (8192 x 1024, K=1024) -> f32
    hgemm<0><<<dim3(DD / 128, MM / 128), 256, HG_SMEM>>>(
        Yh, DI, Wop, nullptr, nullptr, OUTP, nullptr, MM, DD, DI);

    // 8. xnew = x + OUTP[:, path_rev, :]
    add_gather_kernel<<<(int)(((size_t)MM * DD + 255) / 256), 256>>>(x, OUTP, path_rev, XNEW);

    // 9. hn = LN(xnew) -> fp16
    ln_kernel<<<MM, 256>>>(XNEW, nullptr, HNh);

    // 10. G = gelu(hn @ fc1_w^T + fc1_b)   (8192 x 4096, K=1024) -> fp16
    hgemm<1><<<dim3(HH / 128, MM / 128), 256, HG_SMEM>>>(
        HNh, DD, Wf1, fc1_b, nullptr, nullptr, Gh, MM, HH, DD);

    // 11. out = xnew + G @ fc2_w^T + fc2_b   (8192 x 1024, K=4096)
    hgemm<2><<<dim3(DD / 128, MM / 128), 256, HG_SMEM>>>(
        Gh, HH, Wf2, fc2_b, XNEW, out, nullptr, MM, DD, HH);
}

// round 11
// speedup vs baseline: 1.6328x; 1.0339x over previous
#include <cuda_runtime.h>
#include <cuda_fp16.h>
#include <cstdint>

// Problem constants (fixed by setup_inputs)
#define BB 2
#define LL 4096
#define DD 1024
#define DI 1024
#define NS 16
#define RR 64
#define HH 4096
#define MM (BB*LL)          // 8192 rows
#define PROJC (RR + 2*NS)   // 96

// ---------------- scratch ( __device__ globals, no allocation ) -------------
__device__ __half g_Uh  [(size_t)MM * DD];      // LN(gathered x), fp16
__device__ float  g_XZ  [(size_t)MM * 2 * DI];  // in_proj output (xi | z)
__device__ float  g_XC  [(size_t)MM * DI];      // conv + silu (f32 for scan)
__device__ __half g_XCh [(size_t)MM * DI];      // conv + silu (f16 for GEMM)
__device__ float  g_PROJ[(size_t)MM * PROJC];   // x_proj output (f32 for scan B,C)
__device__ __half g_PROJh[(size_t)MM * PROJC];  // fp16 copy for dt GEMM
__device__ float  g_DT  [(size_t)MM * DI];      // softplus(dt)
__device__ __half g_Yh  [(size_t)MM * DI];      // scan output * silu(z), fp16
__device__ float  g_OUTP[(size_t)MM * DD];      // out_proj output
__device__ float  g_XNEW[(size_t)MM * DD];      // x + scattered mamba out
__device__ __half g_HNh [(size_t)MM * DD];      // LN(xnew), fp16
__device__ __half g_Gh  [(size_t)MM * HH];      // gelu(fc1), fp16
// fp16 weights
__device__ __half g_Wip [(size_t)2 * DI * DD];
__device__ __half g_Wxp [(size_t)PROJC * DI];
__device__ __half g_Wdt [(size_t)DI * RR];
__device__ __half g_Wop [(size_t)DD * DI];
__device__ __half g_Wf1 [(size_t)HH * DD];
__device__ __half g_Wf2 [(size_t)DD * HH];

// ---------------- helpers ---------------------------------------------------
__device__ __forceinline__ float silu_f(float x) { return x / (1.0f + __expf(-x)); }
__device__ __forceinline__ float gelu_tanh_f(float x) {
    float u = 0.7978845608028654f * (x + 0.044715f * x * x * x);
    return 0.5f * x * (1.0f + tanhf(u));
}
__device__ __forceinline__ float softplus_f(float x) {
    return (x > 20.0f) ? x : log1pf(expf(x));
}

// ---------------- f32 -> f16 convert ----------------------------------------
__global__ __launch_bounds__(256) void f2h_kernel(const float* __restrict__ s,
                                                  __half* __restrict__ d, int n)
{
    int i = (blockIdx.x * blockDim.x + threadIdx.x) * 4;
    if (i >= n) return;
    float4 v = *(const float4*)(s + i);
    __half2* dp = (__half2*)(d + i);
    dp[0] = __floats2half2_rn(v.x, v.y);
    dp[1] = __floats2half2_rn(v.z, v.w);
}

// ---------------- LayerNorm (optional gather), fp16 out ---------------------
__global__ __launch_bounds__(256) void ln_kernel(
    const float* __restrict__ X, const int* __restrict__ gather,
    __half* __restrict__ Out)
{
    int row = blockIdx.x;
    int b = row >> 12, t = row & (LL - 1);
    int src = gather ? ((b << 12) + gather[t]) : row;
    const float* xp = X + (size_t)src * DD;
    __half* op = Out + (size_t)row * DD;
    __shared__ float sred[8];
    __shared__ float smv[2];
    int tid = threadIdx.x;

    float v[4];
    float s = 0.f;
#pragma unroll
    for (int i = 0; i < 4; i++) { v[i] = xp[tid + i * 256]; s += v[i]; }
#pragma unroll
    for (int o = 16; o; o >>= 1) s += __shfl_xor_sync(0xffffffffu, s, o);
    if ((tid & 31) == 0) sred[tid >> 5] = s;
    __syncthreads();
    if (tid < 8) {
        s = sred[tid];
#pragma unroll
        for (int o = 4; o; o >>= 1) s += __shfl_xor_sync(0xffu, s, o);
        if (tid == 0) smv[0] = s * (1.0f / DD);
    }
    __syncthreads();
    float mean = smv[0];
    float vs = 0.f;
#pragma unroll
    for (int i = 0; i < 4; i++) { float d = v[i] - mean; vs += d * d; }
#pragma unroll
    for (int o = 16; o; o >>= 1) vs += __shfl_xor_sync(0xffffffffu, vs, o);
    __syncthreads();
    if ((tid & 31) == 0) sred[tid >> 5] = vs;
    __syncthreads();
    if (tid < 8) {
        vs = sred[tid];
#pragma unroll
        for (int o = 4; o; o >>= 1) vs += __shfl_xor_sync(0xffu, vs, o);
        if (tid == 0) smv[1] = rsqrtf(vs * (1.0f / DD) + 1e-6f);
    }
    __syncthreads();
    float inv = smv[1];
#pragma unroll
    for (int i = 0; i < 4; i++) op[tid + i * 256] = __float2half((v[i] - mean) * inv);
}

// ---------------- FP16 tensor-core GEMM (mma.sync) ---------------------------
// C[m,n] = epi( sum_k A[m,k]*W[n,k] ), A: MxK half (lda), W: NxK half row-major.
// MODE 0: f32 out   1: gelu(acc+bias)->f16   2: resid+acc+bias->f32
// MODE 3: softplus(acc+bias)->f32            4: dual f32 + f16
// Tile 128x128, BK=32 halfs, 2-stage cp.async (static smem, R4-proven),
// A AND B fragments via ldmatrix (B: 4x ldsm.x4 replaces 16 scalar LDS).

#define BKH 32
#define ROWH 40   // 32 + 8 pad halfs (80B rows: conflict-free)

__device__ __forceinline__ void mma_f16(float c[4], const uint32_t a[4], const uint32_t b[2]) {
    asm volatile(
        "mma.sync.aligned.m16n8k16.row.col.f32.f16.f16.f32 "
        "{%0,%1,%2,%3}, {%4,%5,%6,%7}, {%8,%9}, {%0,%1,%2,%3};\n"
        : "+f"(c[0]), "+f"(c[1]), "+f"(c[2]), "+f"(c[3])
        : "r"(a[0]), "r"(a[1]), "r"(a[2]), "r"(a[3]), "r"(b[0]), "r"(b[1]));
}
__device__ __forceinline__ void ldsm_x4(uint32_t r[4], const void* p) {
    uint32_t s = (uint32_t)__cvta_generic_to_shared(p);
    asm volatile("ldmatrix.sync.aligned.m8n8.x4.shared.b16 {%0,%1,%2,%3}, [%4];\n"
                 : "=r"(r[0]), "=r"(r[1]), "=r"(r[2]), "=r"(r[3]) : "r"(s));
}
__device__ __forceinline__ void cp16(void* dst, const void* src, bool pred) {
    uint32_t d = (uint32_t)__cvta_generic_to_shared(dst);
    int sz = pred ? 16 : 0;
    asm volatile("cp.async.cg.shared.global [%0], [%1], 16, %2;\n"
                 :: "r"(d), "l"(src), "r"(sz));
}

template <int MODE>
__global__ __launch_bounds__(256, 2) void hgemm(
    const __half* __restrict__ A, int lda,
    const __half* __restrict__ W,
    const float* __restrict__ bias,
    const float* __restrict__ resid,
    float* __restrict__ Cf, __half* __restrict__ Ch,
    int M, int N, int K)
{
    __shared__ __half As[2][128][ROWH];
    __shared__ __half Ws[2][128][ROWH];

    int tid  = threadIdx.x;
    int warp = tid >> 5, lane = tid & 31;
    int g = lane >> 2, t = lane & 3;
    int wm = warp >> 1, wn = warp & 1;     // 4 x 2 warp grid
    int row0 = blockIdx.y * 128;
    int col0 = blockIdx.x * 128;

    // global->smem mapping: thread -> (row = tid>>1), two 16B chunks
    int lrow = tid >> 1;
    int lch  = (tid & 1) * 16;             // half offset of first chunk
    const __half* Ag = A + (size_t)(row0 + lrow) * lda + lch;
    int wnrow = col0 + lrow;
    bool wok = (wnrow < N);
    const __half* Wg = W + (size_t)(wok ? wnrow : 0) * K + lch;

    // B ldmatrix addressing: 4 tiles per ldsm.x4:
    //  lanes 0-7  -> (n2p,   ks)    rows n2p+0..7
    //  lanes 8-15 -> (n2p,   ks+8)
    //  lanes 16-23-> (n2p+1, ks)    rows n2p+8..15
    //  lanes 24-31-> (n2p+1, ks+8)
    int brow_off = ((lane >> 4) << 3) + (lane & 7);   // 0..15
    int bcol_off = ((lane >> 3) & 1) * 8;             // 0 or 8

    float acc[2][8][4];
#pragma unroll
    for (int i = 0; i < 2; i++)
#pragma unroll
        for (int j = 0; j < 8; j++)
#pragma unroll
            for (int q = 0; q < 4; q++) acc[i][j][q] = 0.f;

#define LOADST(k0, b)                                                     \
    {                                                                     \
        cp16(&As[b][lrow][lch + 0], Ag + (k0) + 0, true);                 \
        cp16(&As[b][lrow][lch + 8], Ag + (k0) + 8, true);                 \
        cp16(&Ws[b][lrow][lch + 0], Wg + (k0) + 0, wok);                  \
        cp16(&Ws[b][lrow][lch + 8], Wg + (k0) + 8, wok);                  \
        asm volatile("cp.async.commit_group;\n");                         \
    }

#define COMPUTE(b)                                                        \
    {                                                                     \
        _Pragma("unroll")                                                 \
        for (int ks = 0; ks < BKH; ks += 16) {                            \
            uint32_t af[2][4], bf[8][2];                                  \
            _Pragma("unroll")                                             \
            for (int i = 0; i < 2; i++)                                   \
                ldsm_x4(af[i], &As[b][wm * 32 + i * 16 + (lane & 15)]     \
                                   [ks + (lane >> 4) * 8]);               \
            _Pragma("unroll")                                             \
            for (int p = 0; p < 4; p++) {                                 \
                uint32_t br[4];                                           \
                ldsm_x4(br, &Ws[b][wn * 64 + p * 16 + brow_off]           \
                                  [ks + bcol_off]);                       \
                bf[2 * p + 0][0] = br[0];                                 \
                bf[2 * p + 0][1] = br[1];                                 \
                bf[2 * p + 1][0] = br[2];                                 \
                bf[2 * p + 1][1] = br[3];                                 \
            }                                                             \
            _Pragma("unroll")                                             \
            for (int i = 0; i < 2; i++)                                   \
                _Pragma("unroll")                                         \
                for (int j = 0; j < 8; j++)                               \
                    mma_f16(acc[i][j], af[i], bf[j]);                     \
        }                                                                 \
    }

    LOADST(0, 0);
    int buf = 0;
    for (int k0 = BKH; k0 < K; k0 += BKH) {
        LOADST(k0, buf ^ 1);
        asm volatile("cp.async.wait_group 1;\n");
        __syncthreads();
        COMPUTE(buf);
        __syncthreads();
        buf ^= 1;
    }
    asm volatile("cp.async.wait_group 0;\n");
    __syncthreads();
    COMPUTE(buf);

    // epilogue: each thread owns cols (2t, 2t+1), rows g / g+8 per 16-row tile
#pragma unroll
    for (int i = 0; i < 2; i++) {
#pragma unroll
        for (int j = 0; j < 8; j++) {
            int col = col0 + wn * 64 + j * 8 + 2 * t;
            if (col >= N) continue;
            float b0v = 0.f, b1v = 0.f;
            if (MODE == 1 || MODE == 2 || MODE == 3) { b0v = bias[col]; b1v = bias[col + 1]; }
#pragma unroll
            for (int h = 0; h < 2; h++) {
                int row = row0 + wm * 32 + i * 16 + g + h * 8;
                size_t oidx = (size_t)row * N + col;
                float v0 = acc[i][j][2 * h + 0];
                float v1 = acc[i][j][2 * h + 1];
                if (MODE == 1) {
                    v0 = gelu_tanh_f(v0 + b0v); v1 = gelu_tanh_f(v1 + b1v);
                    *(__half2*)(Ch + oidx) = __floats2half2_rn(v0, v1);
                } else if (MODE == 2) {
                    float2 rr = *(const float2*)(resid + oidx);
                    *(float2*)(Cf + oidx) = make_float2(rr.x + v0 + b0v, rr.y + v1 + b1v);
                } else if (MODE == 3) {
                    *(float2*)(Cf + oidx) = make_float2(softplus_f(v0 + b0v),
                                                        softplus_f(v1 + b1v));
                } else if (MODE == 4) {
                    *(float2*)(Cf + oidx) = make_float2(v0, v1);
                    *(__half2*)(Ch + oidx) = __floats2half2_rn(v0, v1);
                } else {
                    *(float2*)(Cf + oidx) = make_float2(v0, v1);
                }
            }
        }
    }
#undef LOADST
#undef COMPUTE
}

// ---------------- depthwise causal conv (D_CONV=4) + silu -------------------
__global__ __launch_bounds__(256) void conv_silu_kernel(
    const float* __restrict__ XZ, const float* __restrict__ conv_w,
    const float* __restrict__ conv_b, float* __restrict__ XC,
    __half* __restrict__ XCh)
{
    size_t idx = (size_t)blockIdx.x * blockDim.x + threadIdx.x;
    if (idx >= (size_t)MM * DI) return;
    int d = (int)(idx & (DI - 1));
    int m = (int)(idx >> 10);
    int t = m & (LL - 1);
    int mb = m - t;
    float acc = conv_b[d];
#pragma unroll
    for (int k = 0; k < 4; k++) {
        int tt = t - 3 + k;
        if (tt >= 0)
            acc = fmaf(conv_w[d * 4 + k], XZ[(size_t)(mb + tt) * (2 * DI) + d], acc);
    }
    float r = silu_f(acc);
    XC[idx] = r;
    XCh[idx] = __float2half(r);
}

// ---------------- selective scan: warp per (b,d), prefetched -----------------
__global__ __launch_bounds__(256) void scan_kernel(
    const float* __restrict__ DT, const float* __restrict__ XC,
    const float* __restrict__ PROJ, const float* __restrict__ XZ,
    const float* __restrict__ A_log, const float* __restrict__ D_param,
    __half* __restrict__ Y)
{
    int wg = (blockIdx.x * blockDim.x + threadIdx.x) >> 5;  // 0..2047
    int lane = threadIdx.x & 31;
    int b = wg >> 10;
    int d = wg & (DI - 1);
    bool act = lane < NS;
    float A_n = act ? -expf(A_log[d * NS + lane]) : 0.f;
    float Dp = D_param[d];

    const float* dtp = DT + (size_t)b * LL * DI + d;
    const float* xcp = XC + (size_t)b * LL * DI + d;
    const float* zp  = XZ + (size_t)b * LL * (2 * DI) + DI + d;
    const float* bcp = PROJ + (size_t)b * LL * PROJC + RR;
    __half* yp = Y + (size_t)b * LL * DI + d;

    float h = 0.f;
    float dt = __ldg(dtp), xc = __ldg(xcp), zv = __ldg(zp), bcv = __ldg(bcp + lane);
    for (int t = 0; t < LL; t++) {
        float ndt = 0.f, nxc = 0.f, nzv = 0.f, nbcv = 0.f;
        if (t + 1 < LL) {
            ndt = __ldg(dtp + DI);
            nxc = __ldg(xcp + DI);
            nzv = __ldg(zp + 2 * DI);
            nbcv = __ldg(bcp + PROJC + lane);
        }
        float Cv = __shfl_down_sync(0xffffffffu, bcv, 16);
        float Bv = act ? bcv : 0.f;
        Cv = act ? Cv : 0.f;

        float dA = __expf(dt * A_n);
        h = fmaf(dA, h, dt * xc * Bv);
        float part = h * Cv;                   // nonzero only in lanes 0-15
#pragma unroll
        for (int o = 8; o; o >>= 1) part += __shfl_xor_sync(0xffffffffu, part, o);
        if (lane == 0) {
            float y = part + Dp * xc;
            *yp = __float2half(y * silu_f(zv));
        }
        dtp += DI; xcp += DI; zp += 2 * DI; bcp += PROJC; yp += DI;
        dt = ndt; xc = nxc; zv = nzv; bcv = nbcv;
    }
}

// ---------------- residual add with gather ----------------------------------
__global__ __launch_bounds__(256) void add_gather_kernel(
    const float* __restrict__ X, const float* __restrict__ OUTP,
    const int* __restrict__ path_rev, float* __restrict__ XNEW)
{
    size_t idx = (size_t)blockIdx.x * blockDim.x + threadIdx.x;
    if (idx >= (size_t)MM * DD) return;
    int d = (int)(idx & (DD - 1));
    int m = (int)(idx >> 10);
    int b = m >> 12, t = m & (LL - 1);
    int src = (b << 12) + path_rev[t];
    XNEW[idx] = X[idx] + OUTP[(size_t)src * DD + d];
}

// ---------------- launch -----------------------------------------------------
extern "C" void kernel_launch(void* const* d_in, const int* in_sizes, int n_in,
                              void* d_out, int out_size)
{
    const float* x          = (const float*)d_in[0];
    const int*   path       = (const int*)  d_in[1];
    const int*   path_rev   = (const int*)  d_in[2];
    const float* in_proj_w  = (const float*)d_in[3];
    const float* conv_w     = (const float*)d_in[4];
    const float* conv_b     = (const float*)d_in[5];
    const float* x_proj_w   = (const float*)d_in[6];
    const float* dt_proj_w  = (const float*)d_in[7];
    const float* dt_proj_b  = (const float*)d_in[8];
    const float* A_log      = (const float*)d_in[9];
    const float* D_param    = (const float*)d_in[10];
    const float* out_proj_w = (const float*)d_in[11];
    const float* fc1_w      = (const float*)d_in[12];
    const float* fc1_b      = (const float*)d_in[13];
    const float* fc2_w      = (const float*)d_in[14];
    const float* fc2_b      = (const float*)d_in[15];
    float* out = (float*)d_out;

    __half *Uh, *XCh, *PROJh, *Yh, *HNh, *Gh;
    __half *Wip, *Wxp, *Wdt, *Wop, *Wf1, *Wf2;
    float *XZ, *XC, *PROJ, *DT, *OUTP, *XNEW;
    cudaGetSymbolAddress((void**)&Uh,    g_Uh);
    cudaGetSymbolAddress((void**)&XZ,    g_XZ);
    cudaGetSymbolAddress((void**)&XC,    g_XC);
    cudaGetSymbolAddress((void**)&XCh,   g_XCh);
    cudaGetSymbolAddress((void**)&PROJ,  g_PROJ);
    cudaGetSymbolAddress((void**)&PROJh, g_PROJh);
    cudaGetSymbolAddress((void**)&DT,    g_DT);
    cudaGetSymbolAddress((void**)&Yh,    g_Yh);
    cudaGetSymbolAddress((void**)&OUTP,  g_OUTP);
    cudaGetSymbolAddress((void**)&XNEW,  g_XNEW);
    cudaGetSymbolAddress((void**)&HNh,   g_HNh);
    cudaGetSymbolAddress((void**)&Gh,    g_Gh);
    cudaGetSymbolAddress((void**)&Wip,   g_Wip);
    cudaGetSymbolAddress((void**)&Wxp,   g_Wxp);
    cudaGetSymbolAddress((void**)&Wdt,   g_Wdt);
    cudaGetSymbolAddress((void**)&Wop,   g_Wop);
    cudaGetSymbolAddress((void**)&Wf1,   g_Wf1);
    cudaGetSymbolAddress((void**)&Wf2,   g_Wf2);

    auto cvt = [&](const float* s, __half* d, int n) {
        f2h_kernel<<<(n / 4 + 255) / 256, 256>>>(s, d, n);
    };

    // Launch order arranged so ncu's captured launch (index 3) is the in_proj hgemm.
    // 0: f2h Wip
    cvt(in_proj_w,  Wip, 2 * DI * DD);
    // 1: u = LN(x[:, path, :]) -> fp16
    ln_kernel<<<MM, 256>>>(x, path, Uh);
    // 2: f2h Wxp (needed only at step 6)
    cvt(x_proj_w,   Wxp, PROJC * DI);
    // 3: xz = u @ in_proj_w^T   (8192 x 2048, K=1024) -> f32   *** profiled ***
    hgemm<0><<<dim3(2 * DI / 128, MM / 128), 256>>>(
        Uh, DD, Wip, nullptr, nullptr, XZ, nullptr, MM, 2 * DI, DD);
    // 4: conv + silu -> f32 + f16
    conv_silu_kernel<<<(int)(((size_t)MM * DI + 255) / 256), 256>>>(XZ, conv_w, conv_b, XC, XCh);
    // 5: f2h Wdt
    cvt(dt_proj_w,  Wdt, DI * RR);
    // 6: proj = xc @ x_proj_w^T   (8192 x 96, K=1024) -> f32 + f16
    hgemm<4><<<dim3(1, MM / 128), 256>>>(
        XCh, DI, Wxp, nullptr, nullptr, PROJ, PROJh, MM, PROJC, DI);
    // 7: dt = softplus(proj[:, :64] @ dt_proj_w^T + b)   (8192 x 1024, K=64)
    hgemm<3><<<dim3(DI / 128, MM / 128), 256>>>(
        PROJh, PROJC, Wdt, dt_proj_b, nullptr, DT, nullptr, MM, DI, RR);
    // 8: selective scan -> Yh
    scan_kernel<<<(BB * DI * 32) / 256, 256>>>(DT, XC, PROJ, XZ, A_log, D_param, Yh);
    // 9: f2h Wop
    cvt(out_proj_w, Wop, DD * DI);
    // 10: OUTP = Y @ out_proj_w^T   (8192 x 1024, K=1024) -> f32
    hgemm<0><<<dim3(DD / 128, MM / 128), 256>>>(
        Yh, DI, Wop, nullptr, nullptr, OUTP, nullptr, MM, DD, DI);
    // 11: xnew = x + OUTP[:, path_rev, :]
    add_gather_kernel<<<(int)(((size_t)MM * DD + 255) / 256), 256>>>(x, OUTP, path_rev, XNEW);
    // 12: hn = LN(xnew) -> fp16
    ln_kernel<<<MM, 256>>>(XNEW, nullptr, HNh);
    // 13: f2h Wf1
    cvt(fc1_w,      Wf1, HH * DD);
    // 14: G = gelu(hn @ fc1_w^T + fc1_b)   (8192 x 4096, K=1024) -> fp16
    hgemm<1><<<dim3(HH / 128, MM / 128), 256>>>(
        HNh, DD, Wf1, fc1_b, nullptr, nullptr, Gh, MM, HH, DD);
    // 15: f2h Wf2
    cvt(fc2_w,      Wf2, DD * HH);
    // 16: out = xnew + G @ fc2_w^T + fc2_b   (8192 x 1024, K=4096)
    hgemm<2><<<dim3(DD / 128, MM / 128), 256>>>(
        Gh, HH, Wf2, fc2_b, XNEW, out, nullptr, MM, DD, HH);
}

// round 12
// speedup vs baseline: 2.6152x; 1.6017x over previous
#include <cuda_runtime.h>
#include <cuda_fp16.h>
#include <cstdint>

// Problem constants (fixed by setup_inputs)
#define BB 2
#define LL 4096
#define DD 1024
#define DI 1024
#define NS 16
#define RR 64
#define HH 4096
#define MM (BB*LL)          // 8192 rows
#define PROJC (RR + 2*NS)   // 96

// ---------------- scratch ( __device__ globals, no allocation ) -------------
__device__ __half g_Uh  [(size_t)MM * DD];      // LN(gathered x), fp16
__device__ float  g_XZ  [(size_t)MM * 2 * DI];  // in_proj output (xi | z)
__device__ float  g_XC  [(size_t)MM * DI];      // conv + silu (f32 for scan)
__device__ __half g_XCh [(size_t)MM * DI];      // conv + silu (f16 for GEMM)
__device__ float  g_PROJ[(size_t)MM * PROJC];   // x_proj output (f32 for scan B,C)
__device__ __half g_PROJh[(size_t)MM * PROJC];  // fp16 copy for dt GEMM
__device__ float  g_DT  [(size_t)MM * DI];      // softplus(dt)
__device__ __half g_Yh  [(size_t)MM * DI];      // scan output * silu(z), fp16
__device__ float  g_OUTP[(size_t)MM * DD];      // out_proj output
__device__ float  g_XNEW[(size_t)MM * DD];      // x + scattered mamba out
__device__ __half g_HNh [(size_t)MM * DD];      // LN(xnew), fp16
__device__ __half g_Gh  [(size_t)MM * HH];      // gelu(fc1), fp16
// fp16 weights
__device__ __half g_Wip [(size_t)2 * DI * DD];
__device__ __half g_Wxp [(size_t)PROJC * DI];
__device__ __half g_Wdt [(size_t)DI * RR];
__device__ __half g_Wop [(size_t)DD * DI];
__device__ __half g_Wf1 [(size_t)HH * DD];
__device__ __half g_Wf2 [(size_t)DD * HH];

// ---------------- helpers ---------------------------------------------------
__device__ __forceinline__ float silu_f(float x) { return x / (1.0f + __expf(-x)); }
__device__ __forceinline__ float gelu_tanh_f(float x) {
    float u = 0.7978845608028654f * (x + 0.044715f * x * x * x);
    return 0.5f * x * (1.0f + tanhf(u));
}
__device__ __forceinline__ float softplus_f(float x) {
    return (x > 20.0f) ? x : log1pf(expf(x));
}

// ---------------- f32 -> f16 convert ----------------------------------------
__global__ __launch_bounds__(256) void f2h_kernel(const float* __restrict__ s,
                                                  __half* __restrict__ d, int n)
{
    int i = (blockIdx.x * blockDim.x + threadIdx.x) * 4;
    if (i >= n) return;
    float4 v = *(const float4*)(s + i);
    __half2* dp = (__half2*)(d + i);
    dp[0] = __floats2half2_rn(v.x, v.y);
    dp[1] = __floats2half2_rn(v.z, v.w);
}

// ---------------- LayerNorm (optional gather), fp16 out ---------------------
__global__ __launch_bounds__(256) void ln_kernel(
    const float* __restrict__ X, const int* __restrict__ gather,
    __half* __restrict__ Out)
{
    int row = blockIdx.x;
    int b = row >> 12, t = row & (LL - 1);
    int src = gather ? ((b << 12) + gather[t]) : row;
    const float* xp = X + (size_t)src * DD;
    __half* op = Out + (size_t)row * DD;
    __shared__ float sred[8];
    __shared__ float smv[2];
    int tid = threadIdx.x;

    float v[4];
    float s = 0.f;
#pragma unroll
    for (int i = 0; i < 4; i++) { v[i] = xp[tid + i * 256]; s += v[i]; }
#pragma unroll
    for (int o = 16; o; o >>= 1) s += __shfl_xor_sync(0xffffffffu, s, o);
    if ((tid & 31) == 0) sred[tid >> 5] = s;
    __syncthreads();
    if (tid < 8) {
        s = sred[tid];
#pragma unroll
        for (int o = 4; o; o >>= 1) s += __shfl_xor_sync(0xffu, s, o);
        if (tid == 0) smv[0] = s * (1.0f / DD);
    }
    __syncthreads();
    float mean = smv[0];
    float vs = 0.f;
#pragma unroll
    for (int i = 0; i < 4; i++) { float d = v[i] - mean; vs += d * d; }
#pragma unroll
    for (int o = 16; o; o >>= 1) vs += __shfl_xor_sync(0xffffffffu, vs, o);
    __syncthreads();
    if ((tid & 31) == 0) sred[tid >> 5] = vs;
    __syncthreads();
    if (tid < 8) {
        vs = sred[tid];
#pragma unroll
        for (int o = 4; o; o >>= 1) vs += __shfl_xor_sync(0xffu, vs, o);
        if (tid == 0) smv[1] = rsqrtf(vs * (1.0f / DD) + 1e-6f);
    }
    __syncthreads();
    float inv = smv[1];
#pragma unroll
    for (int i = 0; i < 4; i++) op[tid + i * 256] = __float2half((v[i] - mean) * inv);
}

// ---------------- FP16 tensor-core GEMM (mma.sync) ---------------------------
// C[m,n] = epi( sum_k A[m,k]*W[n,k] ), A: MxK half (lda), W: NxK half row-major.
// MODE 0: f32 out   1: gelu(acc+bias)->f16   2: resid+acc+bias->f32
// MODE 3: softplus(acc+bias)->f32            4: dual f32 + f16
// Tile 128x128, BK=32 halfs, 2-stage cp.async (static smem),
// A AND B fragments via ldmatrix.

#define BKH 32
#define ROWH 40   // 32 + 8 pad halfs (80B rows: conflict-free)

__device__ __forceinline__ void mma_f16(float c[4], const uint32_t a[4], const uint32_t b[2]) {
    asm volatile(
        "mma.sync.aligned.m16n8k16.row.col.f32.f16.f16.f32 "
        "{%0,%1,%2,%3}, {%4,%5,%6,%7}, {%8,%9}, {%0,%1,%2,%3};\n"
        : "+f"(c[0]), "+f"(c[1]), "+f"(c[2]), "+f"(c[3])
        : "r"(a[0]), "r"(a[1]), "r"(a[2]), "r"(a[3]), "r"(b[0]), "r"(b[1]));
}
__device__ __forceinline__ void ldsm_x4(uint32_t r[4], const void* p) {
    uint32_t s = (uint32_t)__cvta_generic_to_shared(p);
    asm volatile("ldmatrix.sync.aligned.m8n8.x4.shared.b16 {%0,%1,%2,%3}, [%4];\n"
                 : "=r"(r[0]), "=r"(r[1]), "=r"(r[2]), "=r"(r[3]) : "r"(s));
}
__device__ __forceinline__ void cp16(void* dst, const void* src, bool pred) {
    uint32_t d = (uint32_t)__cvta_generic_to_shared(dst);
    int sz = pred ? 16 : 0;
    asm volatile("cp.async.cg.shared.global [%0], [%1], 16, %2;\n"
                 :: "r"(d), "l"(src), "r"(sz));
}

template <int MODE>
__global__ __launch_bounds__(256, 2) void hgemm(
    const __half* __restrict__ A, int lda,
    const __half* __restrict__ W,
    const float* __restrict__ bias,
    const float* __restrict__ resid,
    float* __restrict__ Cf, __half* __restrict__ Ch,
    int M, int N, int K)
{
    __shared__ __half As[2][128][ROWH];
    __shared__ __half Ws[2][128][ROWH];

    int tid  = threadIdx.x;
    int warp = tid >> 5, lane = tid & 31;
    int g = lane >> 2, t = lane & 3;
    int wm = warp >> 1, wn = warp & 1;     // 4 x 2 warp grid
    int row0 = blockIdx.y * 128;
    int col0 = blockIdx.x * 128;

    // global->smem mapping: thread -> (row = tid>>1), two 16B chunks
    int lrow = tid >> 1;
    int lch  = (tid & 1) * 16;             // half offset of first chunk
    const __half* Ag = A + (size_t)(row0 + lrow) * lda + lch;
    int wnrow = col0 + lrow;
    bool wok = (wnrow < N);
    const __half* Wg = W + (size_t)(wok ? wnrow : 0) * K + lch;

    // B ldmatrix addressing
    int brow_off = ((lane >> 4) << 3) + (lane & 7);   // 0..15
    int bcol_off = ((lane >> 3) & 1) * 8;             // 0 or 8

    float acc[2][8][4];
#pragma unroll
    for (int i = 0; i < 2; i++)
#pragma unroll
        for (int j = 0; j < 8; j++)
#pragma unroll
            for (int q = 0; q < 4; q++) acc[i][j][q] = 0.f;

#define LOADST(k0, b)                                                     \
    {                                                                     \
        cp16(&As[b][lrow][lch + 0], Ag + (k0) + 0, true);                 \
        cp16(&As[b][lrow][lch + 8], Ag + (k0) + 8, true);                 \
        cp16(&Ws[b][lrow][lch + 0], Wg + (k0) + 0, wok);                  \
        cp16(&Ws[b][lrow][lch + 8], Wg + (k0) + 8, wok);                  \
        asm volatile("cp.async.commit_group;\n");                         \
    }

#define COMPUTE(b)                                                        \
    {                                                                     \
        _Pragma("unroll")                                                 \
        for (int ks = 0; ks < BKH; ks += 16) {                            \
            uint32_t af[2][4], bf[8][2];                                  \
            _Pragma("unroll")                                             \
            for (int i = 0; i < 2; i++)                                   \
                ldsm_x4(af[i], &As[b][wm * 32 + i * 16 + (lane & 15)]     \
                                   [ks + (lane >> 4) * 8]);               \
            _Pragma("unroll")                                             \
            for (int p = 0; p < 4; p++) {                                 \
                uint32_t br[4];                                           \
                ldsm_x4(br, &Ws[b][wn * 64 + p * 16 + brow_off]           \
                                  [ks + bcol_off]);                       \
                bf[2 * p + 0][0] = br[0];                                 \
                bf[2 * p + 0][1] = br[1];                                 \
                bf[2 * p + 1][0] = br[2];                                 \
                bf[2 * p + 1][1] = br[3];                                 \
            }                                                             \
            _Pragma("unroll")                                             \
            for (int i = 0; i < 2; i++)                                   \
                _Pragma("unroll")                                         \
                for (int j = 0; j < 8; j++)                               \
                    mma_f16(acc[i][j], af[i], bf[j]);                     \
        }                                                                 \
    }

    LOADST(0, 0);
    int buf = 0;
    for (int k0 = BKH; k0 < K; k0 += BKH) {
        LOADST(k0, buf ^ 1);
        asm volatile("cp.async.wait_group 1;\n");
        __syncthreads();
        COMPUTE(buf);
        __syncthreads();
        buf ^= 1;
    }
    asm volatile("cp.async.wait_group 0;\n");
    __syncthreads();
    COMPUTE(buf);

    // epilogue
#pragma unroll
    for (int i = 0; i < 2; i++) {
#pragma unroll
        for (int j = 0; j < 8; j++) {
            int col = col0 + wn * 64 + j * 8 + 2 * t;
            if (col >= N) continue;
            float b0v = 0.f, b1v = 0.f;
            if (MODE == 1 || MODE == 2 || MODE == 3) { b0v = bias[col]; b1v = bias[col + 1]; }
#pragma unroll
            for (int h = 0; h < 2; h++) {
                int row = row0 + wm * 32 + i * 16 + g + h * 8;
                size_t oidx = (size_t)row * N + col;
                float v0 = acc[i][j][2 * h + 0];
                float v1 = acc[i][j][2 * h + 1];
                if (MODE == 1) {
                    v0 = gelu_tanh_f(v0 + b0v); v1 = gelu_tanh_f(v1 + b1v);
                    *(__half2*)(Ch + oidx) = __floats2half2_rn(v0, v1);
                } else if (MODE == 2) {
                    float2 rr = *(const float2*)(resid + oidx);
                    *(float2*)(Cf + oidx) = make_float2(rr.x + v0 + b0v, rr.y + v1 + b1v);
                } else if (MODE == 3) {
                    *(float2*)(Cf + oidx) = make_float2(softplus_f(v0 + b0v),
                                                        softplus_f(v1 + b1v));
                } else if (MODE == 4) {
                    *(float2*)(Cf + oidx) = make_float2(v0, v1);
                    *(__half2*)(Ch + oidx) = __floats2half2_rn(v0, v1);
                } else {
                    *(float2*)(Cf + oidx) = make_float2(v0, v1);
                }
            }
        }
    }
#undef LOADST
#undef COMPUTE
}

// ---------------- depthwise causal conv (D_CONV=4) + silu -------------------
__global__ __launch_bounds__(256) void conv_silu_kernel(
    const float* __restrict__ XZ, const float* __restrict__ conv_w,
    const float* __restrict__ conv_b, float* __restrict__ XC,
    __half* __restrict__ XCh)
{
    size_t idx = (size_t)blockIdx.x * blockDim.x + threadIdx.x;
    if (idx >= (size_t)MM * DI) return;
    int d = (int)(idx & (DI - 1));
    int m = (int)(idx >> 10);
    int t = m & (LL - 1);
    int mb = m - t;
    float acc = conv_b[d];
#pragma unroll
    for (int k = 0; k < 4; k++) {
        int tt = t - 3 + k;
        if (tt >= 0)
            acc = fmaf(conv_w[d * 4 + k], XZ[(size_t)(mb + tt) * (2 * DI) + d], acc);
    }
    float r = silu_f(acc);
    XC[idx] = r;
    XCh[idx] = __float2half(r);
}

// ---------------- selective scan: warp per (b,d), 8-step register pipeline ---
#define TB 8
#define NBLK (LL / TB)
__global__ __launch_bounds__(256) void scan_kernel(
    const float* __restrict__ DT, const float* __restrict__ XC,
    const float* __restrict__ PROJ, const float* __restrict__ XZ,
    const float* __restrict__ A_log, const float* __restrict__ D_param,
    __half* __restrict__ Y)
{
    int wg = (blockIdx.x * blockDim.x + threadIdx.x) >> 5;  // 0..2047
    int lane = threadIdx.x & 31;
    int b = wg >> 10;
    int d = wg & (DI - 1);
    bool act = lane < NS;
    float A_n = act ? -expf(A_log[d * NS + lane]) : 0.f;
    float Dp = D_param[d];

    const float* dtp = DT + (size_t)b * LL * DI + d;
    const float* xcp = XC + (size_t)b * LL * DI + d;
    const float* zp  = XZ + (size_t)b * LL * (2 * DI) + DI + d;
    const float* bcp = PROJ + (size_t)b * LL * PROJC + RR;
    __half* yp = Y + (size_t)b * LL * DI + d;

    float cdt[TB], cxc[TB], czv[TB], cbc[TB];
    float ndt[TB] = {0}, nxc[TB] = {0}, nzv[TB] = {0}, nbc[TB] = {0};

    // preload block 0 (32 independent LDGs -> MLP 32)
#pragma unroll
    for (int i = 0; i < TB; i++) {
        cdt[i] = __ldg(dtp + i * DI);
        cxc[i] = __ldg(xcp + i * DI);
        czv[i] = __ldg(zp + i * 2 * DI);
        cbc[i] = __ldg(bcp + i * PROJC + lane);
    }

    float h = 0.f;
    for (int blk = 0; blk < NBLK; blk++) {
        // issue next block's loads before computing current block
        if (blk + 1 < NBLK) {
            const float* dtn = dtp + (blk + 1) * TB * DI;
            const float* xcn = xcp + (blk + 1) * TB * DI;
            const float* zn  = zp  + (blk + 1) * TB * 2 * DI;
            const float* bcn = bcp + (blk + 1) * TB * PROJC;
#pragma unroll
            for (int i = 0; i < TB; i++) {
                ndt[i] = __ldg(dtn + i * DI);
                nxc[i] = __ldg(xcn + i * DI);
                nzv[i] = __ldg(zn + i * 2 * DI);
                nbc[i] = __ldg(bcn + i * PROJC + lane);
            }
        }
        __half* yb = yp + blk * TB * DI;
#pragma unroll
        for (int i = 0; i < TB; i++) {
            float dt = cdt[i], xc = cxc[i], zv = czv[i], bcv = cbc[i];
            float Cv = __shfl_down_sync(0xffffffffu, bcv, 16);
            float Bv = act ? bcv : 0.f;
            Cv = act ? Cv : 0.f;
            float dA = __expf(dt * A_n);
            h = fmaf(dA, h, dt * xc * Bv);
            float part = h * Cv;               // nonzero only in lanes 0-15
#pragma unroll
            for (int o = 8; o; o >>= 1) part += __shfl_xor_sync(0xffffffffu, part, o);
            if (lane == 0) {
                float y = part + Dp * xc;
                yb[i * DI] = __float2half(y * silu_f(zv));
            }
        }
        // rotate buffers (register moves, renamed by ptxas)
#pragma unroll
        for (int i = 0; i < TB; i++) {
            cdt[i] = ndt[i]; cxc[i] = nxc[i]; czv[i] = nzv[i]; cbc[i] = nbc[i];
        }
    }
}

// ---------------- residual add with gather ----------------------------------
__global__ __launch_bounds__(256) void add_gather_kernel(
    const float* __restrict__ X, const float* __restrict__ OUTP,
    const int* __restrict__ path_rev, float* __restrict__ XNEW)
{
    size_t idx = (size_t)blockIdx.x * blockDim.x + threadIdx.x;
    if (idx >= (size_t)MM * DD) return;
    int d = (int)(idx & (DD - 1));
    int m = (int)(idx >> 10);
    int b = m >> 12, t = m & (LL - 1);
    int src = (b << 12) + path_rev[t];
    XNEW[idx] = X[idx] + OUTP[(size_t)src * DD + d];
}

// ---------------- launch -----------------------------------------------------
extern "C" void kernel_launch(void* const* d_in, const int* in_sizes, int n_in,
                              void* d_out, int out_size)
{
    const float* x          = (const float*)d_in[0];
    const int*   path       = (const int*)  d_in[1];
    const int*   path_rev   = (const int*)  d_in[2];
    const float* in_proj_w  = (const float*)d_in[3];
    const float* conv_w     = (const float*)d_in[4];
    const float* conv_b     = (const float*)d_in[5];
    const float* x_proj_w   = (const float*)d_in[6];
    const float* dt_proj_w  = (const float*)d_in[7];
    const float* dt_proj_b  = (const float*)d_in[8];
    const float* A_log      = (const float*)d_in[9];
    const float* D_param    = (const float*)d_in[10];
    const float* out_proj_w = (const float*)d_in[11];
    const float* fc1_w      = (const float*)d_in[12];
    const float* fc1_b      = (const float*)d_in[13];
    const float* fc2_w      = (const float*)d_in[14];
    const float* fc2_b      = (const float*)d_in[15];
    float* out = (float*)d_out;

    __half *Uh, *XCh, *PROJh, *Yh, *HNh, *Gh;
    __half *Wip, *Wxp, *Wdt, *Wop, *Wf1, *Wf2;
    float *XZ, *XC, *PROJ, *DT, *OUTP, *XNEW;
    cudaGetSymbolAddress((void**)&Uh,    g_Uh);
    cudaGetSymbolAddress((void**)&XZ,    g_XZ);
    cudaGetSymbolAddress((void**)&XC,    g_XC);
    cudaGetSymbolAddress((void**)&XCh,   g_XCh);
    cudaGetSymbolAddress((void**)&PROJ,  g_PROJ);
    cudaGetSymbolAddress((void**)&PROJh, g_PROJh);
    cudaGetSymbolAddress((void**)&DT,    g_DT);
    cudaGetSymbolAddress((void**)&Yh,    g_Yh);
    cudaGetSymbolAddress((void**)&OUTP,  g_OUTP);
    cudaGetSymbolAddress((void**)&XNEW,  g_XNEW);
    cudaGetSymbolAddress((void**)&HNh,   g_HNh);
    cudaGetSymbolAddress((void**)&Gh,    g_Gh);
    cudaGetSymbolAddress((void**)&Wip,   g_Wip);
    cudaGetSymbolAddress((void**)&Wxp,   g_Wxp);
    cudaGetSymbolAddress((void**)&Wdt,   g_Wdt);
    cudaGetSymbolAddress((void**)&Wop,   g_Wop);
    cudaGetSymbolAddress((void**)&Wf1,   g_Wf1);
    cudaGetSymbolAddress((void**)&Wf2,   g_Wf2);

    auto cvt = [&](const float* s, __half* d, int n) {
        f2h_kernel<<<(n / 4 + 255) / 256, 256>>>(s, d, n);
    };

    // 0: f2h Wip
    cvt(in_proj_w,  Wip, 2 * DI * DD);
    // 1: u = LN(x[:, path, :]) -> fp16
    ln_kernel<<<MM, 256>>>(x, path, Uh);
    // 2: f2h Wxp
    cvt(x_proj_w,   Wxp, PROJC * DI);
    // 3: xz = u @ in_proj_w^T   (8192 x 2048, K=1024) -> f32   *** profiled ***
    hgemm<0><<<dim3(2 * DI / 128, MM / 128), 256>>>(
        Uh, DD, Wip, nullptr, nullptr, XZ, nullptr, MM, 2 * DI, DD);
    // 4: conv + silu -> f32 + f16
    conv_silu_kernel<<<(int)(((size_t)MM * DI + 255) / 256), 256>>>(XZ, conv_w, conv_b, XC, XCh);
    // 5: f2h Wdt
    cvt(dt_proj_w,  Wdt, DI * RR);
    // 6: proj = xc @ x_proj_w^T   (8192 x 96, K=1024) -> f32 + f16
    hgemm<4><<<dim3(1, MM / 128), 256>>>(
        XCh, DI, Wxp, nullptr, nullptr, PROJ, PROJh, MM, PROJC, DI);
    // 7: dt = softplus(proj[:, :64] @ dt_proj_w^T + b)   (8192 x 1024, K=64)
    hgemm<3><<<dim3(DI / 128, MM / 128), 256>>>(
        PROJh, PROJC, Wdt, dt_proj_b, nullptr, DT, nullptr, MM, DI, RR);
    // 8: selective scan -> Yh
    scan_kernel<<<(BB * DI * 32) / 256, 256>>>(DT, XC, PROJ, XZ, A_log, D_param, Yh);
    // 9: f2h Wop
    cvt(out_proj_w, Wop, DD * DI);
    // 10: OUTP = Y @ out_proj_w^T   (8192 x 1024, K=1024) -> f32
    hgemm<0><<<dim3(DD / 128, MM / 128), 256>>>(
        Yh, DI, Wop, nullptr, nullptr, OUTP, nullptr, MM, DD, DI);
    // 11: xnew = x + OUTP[:, path_rev, :]
    add_gather_kernel<<<(int)(((size_t)MM * DD + 255) / 256), 256>>>(x, OUTP, path_rev, XNEW);
    // 12: hn = LN(xnew) -> fp16
    ln_kernel<<<MM, 256>>>(XNEW, nullptr, HNh);
    // 13: f2h Wf1
    cvt(fc1_w,      Wf1, HH * DD);
    // 14: G = gelu(hn @ fc1_w^T + fc1_b)   (8192 x 4096, K=1024) -> fp16
    hgemm<1><<<dim3(HH / 128, MM / 128), 256>>>(
        HNh, DD, Wf1, fc1_b, nullptr, nullptr, Gh, MM, HH, DD);
    // 15: f2h Wf2
    cvt(fc2_w,      Wf2, DD * HH);
    // 16: out = xnew + G @ fc2_w^T + fc2_b   (8192 x 1024, K=4096)
    hgemm<2><<<dim3(DD / 128, MM / 128), 256>>>(
        Gh, HH, Wf2, fc2_b, XNEW, out, nullptr, MM, DD, HH);
}